// round 2
// baseline (speedup 1.0000x reference)
#include <cuda_runtime.h>
#include <cstddef>

#define NBATCH 32
#define CH     64
#define LEN    2048
#define OCH    128
#define KCAT   192   // 3*CH

// Scratch for propagated features (16 MB each) — __device__ globals, no allocs.
__device__ float g_y1[(size_t)NBATCH * CH * LEN];
__device__ float g_y2[(size_t)NBATCH * CH * LEN];

// ---------------------------------------------------------------------------
// Propagate: Y[n] = X[n] @ M[n]
//   X: (CH, LEN) row-major, M: (LEN, LEN) row-major, Y: (CH, LEN)
// Tile: BM=64 (full C) x BN=128 x BK=32. 256 threads, 4x8 micro-tile.
// ---------------------------------------------------------------------------
__global__ __launch_bounds__(256, 2)
void propagate_kernel(const float* __restrict__ X,
                      const float* __restrict__ M,
                      float* __restrict__ Y)
{
    __shared__ float As[32][68];    // [k][m]; stride 272B = 17*16 -> float4-aligned rows
    __shared__ float Bs[32][128];   // [k][n]

    const int n  = blockIdx.y;
    const int jt = blockIdx.x * 128;

    const float* Xn = X + (size_t)n * CH * LEN;
    const float* Mn = M + (size_t)n * LEN * LEN;
    float*       Yn = Y + (size_t)n * CH * LEN;

    const int tid  = threadIdx.x;
    const int row0 = (tid >> 4) * 4;   // 0..60
    const int col0 = (tid & 15) * 8;   // 0..120

    float acc[4][8];
#pragma unroll
    for (int i = 0; i < 4; i++)
#pragma unroll
        for (int j = 0; j < 8; j++) acc[i][j] = 0.0f;

    for (int k0 = 0; k0 < LEN; k0 += 32) {
        // Load A tile: 64 rows x 32 k. 512 float4 -> 2 per thread, store transposed.
#pragma unroll
        for (int it = 0; it < 2; it++) {
            int idx = tid + it * 256;          // 0..511
            int r   = idx >> 3;                // row 0..63
            int cq  = idx & 7;                 // float4 index in k
            float4 v = *(const float4*)(Xn + (size_t)r * LEN + k0 + cq * 4);
            As[cq * 4 + 0][r] = v.x;
            As[cq * 4 + 1][r] = v.y;
            As[cq * 4 + 2][r] = v.z;
            As[cq * 4 + 3][r] = v.w;
        }
        // Load B tile: 32 k-rows x 128 cols. 1024 float4 -> 4 per thread.
#pragma unroll
        for (int it = 0; it < 4; it++) {
            int idx = tid + it * 256;          // 0..1023
            int r   = idx >> 5;                // k row 0..31
            int cq  = idx & 31;                // float4 col
            float4 v = *(const float4*)(Mn + (size_t)(k0 + r) * LEN + jt + cq * 4);
            *(float4*)&Bs[r][cq * 4] = v;
        }
        __syncthreads();

#pragma unroll
        for (int kk = 0; kk < 32; kk++) {
            float a[4], b[8];
            *(float4*)a      = *(const float4*)&As[kk][row0];
            *(float4*)&b[0]  = *(const float4*)&Bs[kk][col0];
            *(float4*)&b[4]  = *(const float4*)&Bs[kk][col0 + 4];
#pragma unroll
            for (int i = 0; i < 4; i++)
#pragma unroll
                for (int j = 0; j < 8; j++)
                    acc[i][j] = fmaf(a[i], b[j], acc[i][j]);
        }
        __syncthreads();
    }

#pragma unroll
    for (int i = 0; i < 4; i++) {
        float* dst = Yn + (size_t)(row0 + i) * LEN + jt + col0;
        *(float4*)(dst)     = make_float4(acc[i][0], acc[i][1], acc[i][2], acc[i][3]);
        *(float4*)(dst + 4) = make_float4(acc[i][4], acc[i][5], acc[i][6], acc[i][7]);
    }
}

// ---------------------------------------------------------------------------
// Projection: out[n][o][l] = sum_c W[o][c] * cat[n][c][l] + b[o]
//   cat rows: c<64 -> x, c<128 -> y1, else -> y2.
// Tile: BM=128 (full OUT) x BN=128 x BK=16, K=192. 256 threads, 8x8 micro-tile.
// ---------------------------------------------------------------------------
__global__ __launch_bounds__(256, 2)
void project_kernel(const float* __restrict__ X,
                    const float* __restrict__ Y1,
                    const float* __restrict__ Y2,
                    const float* __restrict__ W,
                    const float* __restrict__ bias,
                    float* __restrict__ out)
{
    __shared__ float Ws[16][132];   // [k][o]; stride 528B = 33*16 -> float4-aligned rows
    __shared__ float Cs[16][128];   // [k][l]

    const int n  = blockIdx.y;
    const int jt = blockIdx.x * 128;

    const float* Xn  = X  + (size_t)n * CH * LEN;
    const float* Y1n = Y1 + (size_t)n * CH * LEN;
    const float* Y2n = Y2 + (size_t)n * CH * LEN;
    float*       On  = out + (size_t)n * OCH * LEN;

    const int tid  = threadIdx.x;
    const int row0 = (tid >> 4) * 8;   // 0..120 (output channel)
    const int col0 = (tid & 15) * 8;   // 0..120 (l within tile)

    float acc[8][8];
#pragma unroll
    for (int i = 0; i < 8; i++)
#pragma unroll
        for (int j = 0; j < 8; j++) acc[i][j] = 0.0f;

    for (int k0 = 0; k0 < KCAT; k0 += 16) {
        // Load W tile: 128 o-rows x 16 c. 512 float4 -> 2 per thread, transposed.
#pragma unroll
        for (int it = 0; it < 2; it++) {
            int idx = tid + it * 256;      // 0..511
            int o   = idx >> 2;            // 0..127
            int kq  = idx & 3;             // float4 index in c
            float4 v = *(const float4*)(W + (size_t)o * KCAT + k0 + kq * 4);
            Ws[kq * 4 + 0][o] = v.x;
            Ws[kq * 4 + 1][o] = v.y;
            Ws[kq * 4 + 2][o] = v.z;
            Ws[kq * 4 + 3][o] = v.w;
        }
        // Load cat tile: 16 channel-rows x 128 l. 512 float4 -> 2 per thread.
#pragma unroll
        for (int it = 0; it < 2; it++) {
            int idx = tid + it * 256;      // 0..511
            int r   = idx >> 5;            // 0..15
            int q   = idx & 31;            // float4 col
            int c   = k0 + r;
            const float* src;
            if (c < CH)            src = Xn  + (size_t)c * LEN;
            else if (c < 2 * CH)   src = Y1n + (size_t)(c - CH) * LEN;
            else                   src = Y2n + (size_t)(c - 2 * CH) * LEN;
            *(float4*)&Cs[r][q * 4] = *(const float4*)(src + jt + q * 4);
        }
        __syncthreads();

#pragma unroll
        for (int kk = 0; kk < 16; kk++) {
            float a[8], b[8];
            *(float4*)&a[0] = *(const float4*)&Ws[kk][row0];
            *(float4*)&a[4] = *(const float4*)&Ws[kk][row0 + 4];
            *(float4*)&b[0] = *(const float4*)&Cs[kk][col0];
            *(float4*)&b[4] = *(const float4*)&Cs[kk][col0 + 4];
#pragma unroll
            for (int i = 0; i < 8; i++)
#pragma unroll
                for (int j = 0; j < 8; j++)
                    acc[i][j] = fmaf(a[i], b[j], acc[i][j]);
        }
        __syncthreads();
    }

#pragma unroll
    for (int i = 0; i < 8; i++) {
        float bv = __ldg(bias + row0 + i);
        float* dst = On + (size_t)(row0 + i) * LEN + jt + col0;
        *(float4*)(dst)     = make_float4(acc[i][0] + bv, acc[i][1] + bv,
                                          acc[i][2] + bv, acc[i][3] + bv);
        *(float4*)(dst + 4) = make_float4(acc[i][4] + bv, acc[i][5] + bv,
                                          acc[i][6] + bv, acc[i][7] + bv);
    }
}

// ---------------------------------------------------------------------------
extern "C" void kernel_launch(void* const* d_in, const int* in_sizes, int n_in,
                              void* d_out, int out_size)
{
    const float* x = (const float*)d_in[0];   // (32, 64, 2048)
    const float* m = (const float*)d_in[1];   // (32, 2048, 2048)
    const float* W = (const float*)d_in[2];   // (128, 192)
    const float* b = (const float*)d_in[3];   // (128,)
    float* out = (float*)d_out;               // (32, 128, 2048)

    float* y1;  cudaGetSymbolAddress((void**)&y1, g_y1);
    float* y2;  cudaGetSymbolAddress((void**)&y2, g_y2);

    dim3 pgrid(LEN / 128, NBATCH);
    propagate_kernel<<<pgrid, 256>>>(x,  m, y1);
    propagate_kernel<<<pgrid, 256>>>(y1, m, y2);

    dim3 ogrid(LEN / 128, NBATCH);
    project_kernel<<<ogrid, 256>>>(x, y1, y2, W, b, out);
}

// round 3
// speedup vs baseline: 1.5445x; 1.5445x over previous
#include <cuda_runtime.h>
#include <cstddef>

#define NBATCH 32
#define CH     64
#define LEN    2048
#define OCH    128
#define KCAT   192   // 3*CH

// Scratch for propagated features (16 MB each) — __device__ globals, no allocs.
__device__ float g_y1[(size_t)NBATCH * CH * LEN];
__device__ float g_y2[(size_t)NBATCH * CH * LEN];

// ---- packed fp32x2 helpers (Blackwell FFMA2 — only reachable via PTX) -----
__device__ __forceinline__ unsigned long long f2_pack(float lo, float hi) {
    unsigned long long r;
    asm("mov.b64 %0, {%1, %2};" : "=l"(r) : "f"(lo), "f"(hi));
    return r;
}
__device__ __forceinline__ void f2_unpack(unsigned long long v, float& lo, float& hi) {
    asm("mov.b64 {%0, %1}, %2;" : "=f"(lo), "=f"(hi) : "l"(v));
}
__device__ __forceinline__ unsigned long long f2_fma(unsigned long long a,
                                                     unsigned long long b,
                                                     unsigned long long c) {
    unsigned long long d;
    asm("fma.rn.f32x2 %0, %1, %2, %3;" : "=l"(d) : "l"(a), "l"(b), "l"(c));
    return d;
}

// ---------------------------------------------------------------------------
// Propagate: Y[n] = X[n] @ M[n]
//   X: (CH, LEN) row-major, M: (LEN, LEN) row-major, Y: (CH, LEN)
// Tile: BM=64 (full C) x BN=256 x BK=16. 256 threads (8 warps), 8x8 micro-tile.
// Accumulators packed as f32x2 pairs along j -> FFMA2.
// Grid = 8 x 32 = 256 CTAs, all resident at 2 CTA/SM (single wave).
// ---------------------------------------------------------------------------
__global__ __launch_bounds__(256, 2)
void propagate_kernel(const float* __restrict__ X,
                      const float* __restrict__ M,
                      float* __restrict__ Y)
{
    __shared__ float As[16][72];    // [k][c]; row stride 288B (16B multiple)
    __shared__ float Bs[16][256];   // [k][j]

    const int n  = blockIdx.y;
    const int jt = blockIdx.x * 256;

    const float* Xn = X + (size_t)n * CH * LEN;
    const float* Mn = M + (size_t)n * LEN * LEN;
    float*       Yn = Y + (size_t)n * CH * LEN;

    const int tid  = threadIdx.x;
    const int row0 = (tid >> 5) * 8;   // warp id * 8 -> c rows (A broadcast per warp)
    const int col0 = (tid & 31) * 8;   // lane * 8    -> j cols

    // ---- loader indices ----
    const int ar = tid >> 2;           // 0..63  (c row for A load)
    const int ac = (tid & 3) * 4;      // 0,4,8,12 (k float4 within BK=16)
    // B: 16 rows x 64 float4 -> 4 float4 per thread
    int br[4], bc[4];
#pragma unroll
    for (int it = 0; it < 4; it++) {
        int idx = tid + it * 256;      // 0..1023
        br[it] = idx >> 6;             // k row 0..15
        bc[it] = (idx & 63) * 4;       // j col
    }

    // ---- initial prefetch ----
    float4 a_reg = *(const float4*)(Xn + (size_t)ar * LEN + ac);
    float4 b_reg[4];
#pragma unroll
    for (int it = 0; it < 4; it++)
        b_reg[it] = *(const float4*)(Mn + (size_t)br[it] * LEN + jt + bc[it]);

    unsigned long long acc[8][4];
#pragma unroll
    for (int i = 0; i < 8; i++)
#pragma unroll
        for (int q = 0; q < 4; q++) acc[i][q] = 0ull;

    for (int k0 = 0; k0 < LEN; k0 += 16) {
        // commit staged tiles to smem
        As[ac + 0][ar] = a_reg.x;
        As[ac + 1][ar] = a_reg.y;
        As[ac + 2][ar] = a_reg.z;
        As[ac + 3][ar] = a_reg.w;
#pragma unroll
        for (int it = 0; it < 4; it++)
            *(float4*)&Bs[br[it]][bc[it]] = b_reg[it];
        __syncthreads();

        // prefetch next K-slab (hidden under compute)
        if (k0 + 16 < LEN) {
            a_reg = *(const float4*)(Xn + (size_t)ar * LEN + (k0 + 16) + ac);
#pragma unroll
            for (int it = 0; it < 4; it++)
                b_reg[it] = *(const float4*)(Mn + (size_t)(k0 + 16 + br[it]) * LEN + jt + bc[it]);
        }

        // compute
#pragma unroll
        for (int kk = 0; kk < 16; kk++) {
            float a[8];
            *(float4*)&a[0] = *(const float4*)&As[kk][row0];       // broadcast
            *(float4*)&a[4] = *(const float4*)&As[kk][row0 + 4];
            unsigned long long b2[4];
            {   // b pairs load directly as 64-bit words (j-contiguous)
                ulonglong2 t0 = *(const ulonglong2*)&Bs[kk][col0];
                ulonglong2 t1 = *(const ulonglong2*)&Bs[kk][col0 + 4];
                b2[0] = t0.x; b2[1] = t0.y; b2[2] = t1.x; b2[3] = t1.y;
            }
#pragma unroll
            for (int i = 0; i < 8; i++) {
                unsigned long long a2 = f2_pack(a[i], a[i]);
#pragma unroll
                for (int q = 0; q < 4; q++)
                    acc[i][q] = f2_fma(a2, b2[q], acc[i][q]);
            }
        }
        __syncthreads();
    }

    // ---- epilogue: unpack pairs, store 2x float4 per row ----
#pragma unroll
    for (int i = 0; i < 8; i++) {
        float4 v0, v1;
        f2_unpack(acc[i][0], v0.x, v0.y);
        f2_unpack(acc[i][1], v0.z, v0.w);
        f2_unpack(acc[i][2], v1.x, v1.y);
        f2_unpack(acc[i][3], v1.z, v1.w);
        float* dst = Yn + (size_t)(row0 + i) * LEN + jt + col0;
        *(float4*)(dst)     = v0;
        *(float4*)(dst + 4) = v1;
    }
}

// ---------------------------------------------------------------------------
// Projection: out[n][o][l] = sum_c W[o][c] * cat[n][c][l] + b[o]
//   cat rows: c<64 -> x, c<128 -> y1, else -> y2.  (unchanged, known-good)
// ---------------------------------------------------------------------------
__global__ __launch_bounds__(256, 2)
void project_kernel(const float* __restrict__ X,
                    const float* __restrict__ Y1,
                    const float* __restrict__ Y2,
                    const float* __restrict__ W,
                    const float* __restrict__ bias,
                    float* __restrict__ out)
{
    __shared__ float Ws[16][132];   // [k][o]; stride 528B (16B multiple)
    __shared__ float Cs[16][128];   // [k][l]

    const int n  = blockIdx.y;
    const int jt = blockIdx.x * 128;

    const float* Xn  = X  + (size_t)n * CH * LEN;
    const float* Y1n = Y1 + (size_t)n * CH * LEN;
    const float* Y2n = Y2 + (size_t)n * CH * LEN;
    float*       On  = out + (size_t)n * OCH * LEN;

    const int tid  = threadIdx.x;
    const int row0 = (tid >> 4) * 8;   // output channel
    const int col0 = (tid & 15) * 8;   // l within tile

    float acc[8][8];
#pragma unroll
    for (int i = 0; i < 8; i++)
#pragma unroll
        for (int j = 0; j < 8; j++) acc[i][j] = 0.0f;

    for (int k0 = 0; k0 < KCAT; k0 += 16) {
#pragma unroll
        for (int it = 0; it < 2; it++) {
            int idx = tid + it * 256;      // 0..511
            int o   = idx >> 2;            // 0..127
            int kq  = idx & 3;             // float4 index in c
            float4 v = *(const float4*)(W + (size_t)o * KCAT + k0 + kq * 4);
            Ws[kq * 4 + 0][o] = v.x;
            Ws[kq * 4 + 1][o] = v.y;
            Ws[kq * 4 + 2][o] = v.z;
            Ws[kq * 4 + 3][o] = v.w;
        }
#pragma unroll
        for (int it = 0; it < 2; it++) {
            int idx = tid + it * 256;      // 0..511
            int r   = idx >> 5;            // 0..15
            int q   = idx & 31;            // float4 col
            int c   = k0 + r;
            const float* src;
            if (c < CH)            src = Xn  + (size_t)c * LEN;
            else if (c < 2 * CH)   src = Y1n + (size_t)(c - CH) * LEN;
            else                   src = Y2n + (size_t)(c - 2 * CH) * LEN;
            *(float4*)&Cs[r][q * 4] = *(const float4*)(src + jt + q * 4);
        }
        __syncthreads();

#pragma unroll
        for (int kk = 0; kk < 16; kk++) {
            float a[8], b[8];
            *(float4*)&a[0] = *(const float4*)&Ws[kk][row0];
            *(float4*)&a[4] = *(const float4*)&Ws[kk][row0 + 4];
            *(float4*)&b[0] = *(const float4*)&Cs[kk][col0];
            *(float4*)&b[4] = *(const float4*)&Cs[kk][col0 + 4];
#pragma unroll
            for (int i = 0; i < 8; i++)
#pragma unroll
                for (int j = 0; j < 8; j++)
                    acc[i][j] = fmaf(a[i], b[j], acc[i][j]);
        }
        __syncthreads();
    }

#pragma unroll
    for (int i = 0; i < 8; i++) {
        float bv = __ldg(bias + row0 + i);
        float* dst = On + (size_t)(row0 + i) * LEN + jt + col0;
        *(float4*)(dst)     = make_float4(acc[i][0] + bv, acc[i][1] + bv,
                                          acc[i][2] + bv, acc[i][3] + bv);
        *(float4*)(dst + 4) = make_float4(acc[i][4] + bv, acc[i][5] + bv,
                                          acc[i][6] + bv, acc[i][7] + bv);
    }
}

// ---------------------------------------------------------------------------
extern "C" void kernel_launch(void* const* d_in, const int* in_sizes, int n_in,
                              void* d_out, int out_size)
{
    const float* x = (const float*)d_in[0];   // (32, 64, 2048)
    const float* m = (const float*)d_in[1];   // (32, 2048, 2048)
    const float* W = (const float*)d_in[2];   // (128, 192)
    const float* b = (const float*)d_in[3];   // (128,)
    float* out = (float*)d_out;               // (32, 128, 2048)

    float* y1;  cudaGetSymbolAddress((void**)&y1, g_y1);
    float* y2;  cudaGetSymbolAddress((void**)&y2, g_y2);

    dim3 pgrid(LEN / 256, NBATCH);
    propagate_kernel<<<pgrid, 256>>>(x,  m, y1);
    propagate_kernel<<<pgrid, 256>>>(y1, m, y2);

    dim3 ogrid(LEN / 128, NBATCH);
    project_kernel<<<ogrid, 256>>>(x, y1, y2, W, b, out);
}

// round 6
// speedup vs baseline: 2.2425x; 1.4520x over previous
#include <cuda_runtime.h>
#include <cstdint>
#include <cstddef>

#define NBATCH 32
#define CH     64
#define LEN    2048
#define OCH    128
#define KCAT   192

// Scratch (16 MB each) — __device__ globals, no allocs.
__device__ float g_y1[(size_t)NBATCH * CH * LEN];
__device__ float g_y2[(size_t)NBATCH * CH * LEN];

// ===================== helpers (base-ISA only: sm_80+) =====================
__device__ __forceinline__ uint32_t smem_u32(const void* p) {
    uint32_t a;
    asm("{ .reg .u64 t; cvta.to.shared.u64 t, %1; cvt.u32.u64 %0, t; }"
        : "=r"(a) : "l"(p));
    return a;
}
__device__ __forceinline__ float tf32_rn(float x) {
    uint32_t r;
    asm("cvt.rna.tf32.f32 %0, %1;" : "=r"(r) : "f"(x));   // dest is .b32
    return __uint_as_float(r);
}
__device__ __forceinline__ void ldsm_x4(uint32_t addr, uint32_t r[4]) {
    asm volatile("ldmatrix.sync.aligned.m8n8.x4.shared.b16 {%0,%1,%2,%3}, [%4];"
                 : "=r"(r[0]), "=r"(r[1]), "=r"(r[2]), "=r"(r[3]) : "r"(addr));
}
__device__ __forceinline__ void ldsm_x2(uint32_t addr, uint32_t r[2]) {
    asm volatile("ldmatrix.sync.aligned.m8n8.x2.shared.b16 {%0,%1}, [%2];"
                 : "=r"(r[0]), "=r"(r[1]) : "r"(addr));
}
__device__ __forceinline__ void mma_tf32(float c[4], const uint32_t a[4],
                                         const uint32_t b[2]) {
    asm volatile(
        "mma.sync.aligned.m16n8k8.row.col.f32.tf32.tf32.f32 "
        "{%0,%1,%2,%3}, {%4,%5,%6,%7}, {%8,%9}, {%0,%1,%2,%3};"
        : "+f"(c[0]), "+f"(c[1]), "+f"(c[2]), "+f"(c[3])
        : "r"(a[0]), "r"(a[1]), "r"(a[2]), "r"(a[3]), "r"(b[0]), "r"(b[1]));
}

// ---------------------------------------------------------------------------
// Propagate via legacy-path TF32 HMMA:
//   Y[n] = X[n] @ M[n];  D[c][j] = sum_k A[c][k] * B[j][k]
//   A[c][k] = x[c][k] (natural), B[j][k] = m[k][j] (register-transposed).
// CTA tile: BM=64 (all C) x BN=128 x BK=32. 8 warps as 2(m) x 4(n):
//   warp -> m32 (2 x m16 frags) x n32 (4 x n8 frags) -> 8 mma per k8 step.
// ---------------------------------------------------------------------------
__global__ __launch_bounds__(256, 2)
void propagate_mma(const float* __restrict__ X,
                   const float* __restrict__ M,
                   float* __restrict__ Y)
{
    __shared__ __align__(16) float As[64][36];    // [c][k], row 144B
    __shared__ __align__(16) float Bs[128][36];   // [j][k], row 144B

    const int tid  = threadIdx.x;
    const int lane = tid & 31;
    const int wid  = tid >> 5;
    const int n    = blockIdx.y;
    const int jt   = blockIdx.x * 128;

    const int c0w = (wid >> 2) * 32;   // warp m origin (0 or 32)
    const int n0w = (wid & 3) * 32;    // warp n origin (0,32,64,96)

    const float* Xn = X + (size_t)n * CH * LEN;
    const float* Mn = M + (size_t)n * LEN * LEN;
    float*       Yn = Y + (size_t)n * CH * LEN;

    // ---- loader indices ----
    // A: straight copy, 512 float4 over 2 iters: c = idx>>3, q = idx&7
    // B: transpose; thread owns 4x4 block: jq = tid>>3 (0..31), kq = tid&7
    const int jq = tid >> 3, kq = tid & 7;

    float4 a_pre[2];
    float4 b_pre[4];

    // prefetch chunk 0
#pragma unroll
    for (int it = 0; it < 2; it++) {
        int idx = tid + it * 256;
        a_pre[it] = *(const float4*)(Xn + (size_t)(idx >> 3) * LEN + (idx & 7) * 4);
    }
#pragma unroll
    for (int r = 0; r < 4; r++)
        b_pre[r] = *(const float4*)(Mn + (size_t)(4 * kq + r) * LEN + jt + 4 * jq);

    // ldmatrix per-lane base addresses
    const uint32_t aBase = smem_u32(&As[0][0])
        + (uint32_t)(c0w + (lane & 15)) * 144 + ((lane >> 4) & 1) * 16;
    const uint32_t bBase = smem_u32(&Bs[0][0])
        + (uint32_t)(n0w + (lane & 7)) * 144 + ((lane >> 3) & 1) * 16;

    float acc[2][4][4];
#pragma unroll
    for (int f = 0; f < 2; f++)
#pragma unroll
        for (int t = 0; t < 4; t++)
#pragma unroll
            for (int e = 0; e < 4; e++) acc[f][t][e] = 0.0f;

    for (int ch = 0; ch < 64; ch++) {
        __syncthreads();   // previous compute done before overwriting tiles

        // ---- STS A (tf32-rounded) ----
#pragma unroll
        for (int it = 0; it < 2; it++) {
            int idx = tid + it * 256;
            float4 v = a_pre[it];
            v.x = tf32_rn(v.x); v.y = tf32_rn(v.y);
            v.z = tf32_rn(v.z); v.w = tf32_rn(v.w);
            *(float4*)&As[idx >> 3][(idx & 7) * 4] = v;
        }
        // ---- STS B: register 4x4 transpose (tf32-rounded) ----
#pragma unroll
        for (int e = 0; e < 4; e++) {
            float4 w;
            w.x = tf32_rn(((const float*)&b_pre[0])[e]);
            w.y = tf32_rn(((const float*)&b_pre[1])[e]);
            w.z = tf32_rn(((const float*)&b_pre[2])[e]);
            w.w = tf32_rn(((const float*)&b_pre[3])[e]);
            *(float4*)&Bs[4 * jq + e][4 * kq] = w;
        }
        __syncthreads();

        // ---- prefetch chunk ch+1 (overlaps compute below) ----
        if (ch + 1 < 64) {
            const int k0 = (ch + 1) * 32;
#pragma unroll
            for (int it = 0; it < 2; it++) {
                int idx = tid + it * 256;
                a_pre[it] = *(const float4*)(Xn + (size_t)(idx >> 3) * LEN + k0 + (idx & 7) * 4);
            }
#pragma unroll
            for (int r = 0; r < 4; r++)
                b_pre[r] = *(const float4*)(Mn + (size_t)(k0 + 4 * kq + r) * LEN + jt + 4 * jq);
        }

        // ---- compute: 4 k8 steps ----
#pragma unroll
        for (int ks = 0; ks < 4; ks++) {
            uint32_t af[2][4];
            ldsm_x4(aBase + ks * 32, af[0]);
            ldsm_x4(aBase + 2304 + ks * 32, af[1]);   // +16 rows * 144B
            uint32_t bf[4][2];
#pragma unroll
            for (int t = 0; t < 4; t++)
                ldsm_x2(bBase + t * 1152 + ks * 32, bf[t]);  // +8 rows * 144B
#pragma unroll
            for (int f = 0; f < 2; f++)
#pragma unroll
                for (int t = 0; t < 4; t++)
                    mma_tf32(acc[f][t], af[f], bf[t]);
        }
    }

    // ---- epilogue: D[c][j] -> Y[c][jt+j] ----
    const int r0 = lane >> 2, cp = (lane & 3) * 2;
#pragma unroll
    for (int f = 0; f < 2; f++) {
        const int c = c0w + f * 16 + r0;
#pragma unroll
        for (int t = 0; t < 4; t++) {
            const int j = jt + n0w + t * 8 + cp;
            *(float2*)(Yn + (size_t)c * LEN + j) =
                make_float2(acc[f][t][0], acc[f][t][1]);
            *(float2*)(Yn + (size_t)(c + 8) * LEN + j) =
                make_float2(acc[f][t][2], acc[f][t][3]);
        }
    }
}

// ---------------------------------------------------------------------------
// Projection (SIMT, known-good): out[n][o][l] = sum_c W[o][c]*cat[n][c][l] + b[o]
// ---------------------------------------------------------------------------
__global__ __launch_bounds__(256, 2)
void project_kernel(const float* __restrict__ X,
                    const float* __restrict__ Y1,
                    const float* __restrict__ Y2,
                    const float* __restrict__ W,
                    const float* __restrict__ bias,
                    float* __restrict__ out)
{
    __shared__ float Ws[16][132];
    __shared__ float Cs[16][128];

    const int n  = blockIdx.y;
    const int jt = blockIdx.x * 128;

    const float* Xn  = X  + (size_t)n * CH * LEN;
    const float* Y1n = Y1 + (size_t)n * CH * LEN;
    const float* Y2n = Y2 + (size_t)n * CH * LEN;
    float*       On  = out + (size_t)n * OCH * LEN;

    const int tid  = threadIdx.x;
    const int row0 = (tid >> 4) * 8;
    const int col0 = (tid & 15) * 8;

    float acc[8][8];
#pragma unroll
    for (int i = 0; i < 8; i++)
#pragma unroll
        for (int j = 0; j < 8; j++) acc[i][j] = 0.0f;

    for (int k0 = 0; k0 < KCAT; k0 += 16) {
#pragma unroll
        for (int it = 0; it < 2; it++) {
            int idx = tid + it * 256;
            int o   = idx >> 2;
            int kq  = idx & 3;
            float4 v = *(const float4*)(W + (size_t)o * KCAT + k0 + kq * 4);
            Ws[kq * 4 + 0][o] = v.x;
            Ws[kq * 4 + 1][o] = v.y;
            Ws[kq * 4 + 2][o] = v.z;
            Ws[kq * 4 + 3][o] = v.w;
        }
#pragma unroll
        for (int it = 0; it < 2; it++) {
            int idx = tid + it * 256;
            int r   = idx >> 5;
            int q   = idx & 31;
            int c   = k0 + r;
            const float* src;
            if (c < CH)            src = Xn  + (size_t)c * LEN;
            else if (c < 2 * CH)   src = Y1n + (size_t)(c - CH) * LEN;
            else                   src = Y2n + (size_t)(c - 2 * CH) * LEN;
            *(float4*)&Cs[r][q * 4] = *(const float4*)(src + jt + q * 4);
        }
        __syncthreads();

#pragma unroll
        for (int kk = 0; kk < 16; kk++) {
            float a[8], b[8];
            *(float4*)&a[0] = *(const float4*)&Ws[kk][row0];
            *(float4*)&a[4] = *(const float4*)&Ws[kk][row0 + 4];
            *(float4*)&b[0] = *(const float4*)&Cs[kk][col0];
            *(float4*)&b[4] = *(const float4*)&Cs[kk][col0 + 4];
#pragma unroll
            for (int i = 0; i < 8; i++)
#pragma unroll
                for (int j = 0; j < 8; j++)
                    acc[i][j] = fmaf(a[i], b[j], acc[i][j]);
        }
        __syncthreads();
    }

#pragma unroll
    for (int i = 0; i < 8; i++) {
        float bv = __ldg(bias + row0 + i);
        float* dst = On + (size_t)(row0 + i) * LEN + jt + col0;
        *(float4*)(dst)     = make_float4(acc[i][0] + bv, acc[i][1] + bv,
                                          acc[i][2] + bv, acc[i][3] + bv);
        *(float4*)(dst + 4) = make_float4(acc[i][4] + bv, acc[i][5] + bv,
                                          acc[i][6] + bv, acc[i][7] + bv);
    }
}

// ---------------------------------------------------------------------------
extern "C" void kernel_launch(void* const* d_in, const int* in_sizes, int n_in,
                              void* d_out, int out_size)
{
    const float* x = (const float*)d_in[0];   // (32, 64, 2048)
    const float* m = (const float*)d_in[1];   // (32, 2048, 2048)
    const float* W = (const float*)d_in[2];   // (128, 192)
    const float* b = (const float*)d_in[3];   // (128,)
    float* out = (float*)d_out;               // (32, 128, 2048)

    float* y1;  cudaGetSymbolAddress((void**)&y1, g_y1);
    float* y2;  cudaGetSymbolAddress((void**)&y2, g_y2);

    dim3 pgrid(LEN / 128, NBATCH);   // 16 x 32 = 512 CTAs
    propagate_mma<<<pgrid, 256>>>(x,  m, y1);
    propagate_mma<<<pgrid, 256>>>(y1, m, y2);

    dim3 ogrid(LEN / 128, NBATCH);
    project_kernel<<<ogrid, 256>>>(x, y1, y2, W, b, out);
}

// round 7
// speedup vs baseline: 2.4110x; 1.0751x over previous
#include <cuda_runtime.h>
#include <cstdint>
#include <cstddef>

#define NBATCH 32
#define CH     64
#define LEN    2048
#define OCH    128
#define KCAT   192

// Scratch (16 MB each) — __device__ globals, no allocs.
__device__ float g_y1[(size_t)NBATCH * CH * LEN];
__device__ float g_y2[(size_t)NBATCH * CH * LEN];

// ===================== helpers (base-ISA only: sm_80+) =====================
__device__ __forceinline__ uint32_t smem_u32(const void* p) {
    uint32_t a;
    asm("{ .reg .u64 t; cvta.to.shared.u64 t, %1; cvt.u32.u64 %0, t; }"
        : "=r"(a) : "l"(p));
    return a;
}
__device__ __forceinline__ float tf32_rn(float x) {
    uint32_t r;
    asm("cvt.rna.tf32.f32 %0, %1;" : "=r"(r) : "f"(x));
    return __uint_as_float(r);
}
__device__ __forceinline__ void ldsm_x4(uint32_t addr, uint32_t r[4]) {
    asm volatile("ldmatrix.sync.aligned.m8n8.x4.shared.b16 {%0,%1,%2,%3}, [%4];"
                 : "=r"(r[0]), "=r"(r[1]), "=r"(r[2]), "=r"(r[3]) : "r"(addr));
}
__device__ __forceinline__ void mma_tf32(float c[4], const uint32_t a[4],
                                         uint32_t b0, uint32_t b1) {
    asm volatile(
        "mma.sync.aligned.m16n8k8.row.col.f32.tf32.tf32.f32 "
        "{%0,%1,%2,%3}, {%4,%5,%6,%7}, {%8,%9}, {%0,%1,%2,%3};"
        : "+f"(c[0]), "+f"(c[1]), "+f"(c[2]), "+f"(c[3])
        : "r"(a[0]), "r"(a[1]), "r"(a[2]), "r"(a[3]), "r"(b0), "r"(b1));
}

// Tile geometry: BM=64, BN=128, BK=32. Rows padded to 36 floats (144 B):
// ldmatrix rows land on distinct banks (36 mod 32 = 4), STS phases conflict-free.
#define AROW     36
#define A_FLOATS (64  * AROW)      // 2304 floats = 9216 B / stage
#define B_FLOATS (128 * AROW)      // 4608 floats = 18432 B / stage
#define SMEM_FLOATS (2 * A_FLOATS + 2 * B_FLOATS)   // 13824 floats = 55296 B

// ---------------------------------------------------------------------------
// Propagate via TF32 HMMA (legacy mma.sync path), 2-stage smem pipeline.
//   D[c][j] = sum_k A[c][k]*B[j][k];  A = x (natural), B = m^T (reg transpose).
// 8 warps as 2(m) x 4(n); warp tile m32 x n32; 64 chunks of BK=32.
// ---------------------------------------------------------------------------
__global__ __launch_bounds__(256, 2)
void propagate_mma(const float* __restrict__ X,
                   const float* __restrict__ M,
                   float* __restrict__ Y)
{
    extern __shared__ __align__(16) float smem[];
    const uint32_t sbase = smem_u32(smem);

    const int tid  = threadIdx.x;
    const int lane = tid & 31;
    const int wid  = tid >> 5;
    const int n    = blockIdx.y;
    const int jt   = blockIdx.x * 128;

    const int c0w = (wid >> 2) * 32;   // warp m origin (0 / 32)
    const int n0w = (wid & 3) * 32;    // warp n origin (0,32,64,96)

    const float* Xn = X + (size_t)n * CH * LEN;
    const float* Mn = M + (size_t)n * LEN * LEN;
    float*       Yn = Y + (size_t)n * CH * LEN;

    // loader indices: A straight copy (c=idx>>3, q=idx&7);
    // B transpose, thread owns 4x4 block (jq=tid>>3, kq=tid&7)
    const int jq = tid >> 3, kq = tid & 7;

    // per-lane ldmatrix base offsets (stage 0)
    const uint32_t aOff = (uint32_t)(c0w + (lane & 15)) * 144 + ((lane >> 4) & 1) * 16;
    const uint32_t bOff = (uint32_t)(n0w + (lane & 7)) * 144
                        + ((lane >> 3) & 1) * 16 + (lane >> 4) * 32;  // x4: mats 2,3 at +32B (next k8)

    float4 a_pre[2];
    float4 b_pre[4];

    // ---- prefetch + commit chunk 0 into stage 0 ----
#pragma unroll
    for (int it = 0; it < 2; it++) {
        int idx = tid + it * 256;
        a_pre[it] = *(const float4*)(Xn + (size_t)(idx >> 3) * LEN + (idx & 7) * 4);
    }
#pragma unroll
    for (int r = 0; r < 4; r++)
        b_pre[r] = *(const float4*)(Mn + (size_t)(4 * kq + r) * LEN + jt + 4 * jq);

    {
        float* As = smem;
        float* Bs = smem + 2 * A_FLOATS;
#pragma unroll
        for (int it = 0; it < 2; it++) {
            int idx = tid + it * 256;
            float4 v = a_pre[it];
            v.x = tf32_rn(v.x); v.y = tf32_rn(v.y);
            v.z = tf32_rn(v.z); v.w = tf32_rn(v.w);
            *(float4*)&As[(idx >> 3) * AROW + (idx & 7) * 4] = v;
        }
#pragma unroll
        for (int e = 0; e < 4; e++) {
            float4 w;
            w.x = tf32_rn(((const float*)&b_pre[0])[e]);
            w.y = tf32_rn(((const float*)&b_pre[1])[e]);
            w.z = tf32_rn(((const float*)&b_pre[2])[e]);
            w.w = tf32_rn(((const float*)&b_pre[3])[e]);
            *(float4*)&Bs[(4 * jq + e) * AROW + 4 * kq] = w;
        }
    }
    __syncthreads();

    float acc[2][4][4];
#pragma unroll
    for (int f = 0; f < 2; f++)
#pragma unroll
        for (int t = 0; t < 4; t++)
#pragma unroll
            for (int e = 0; e < 4; e++) acc[f][t][e] = 0.0f;

    for (int ch = 0; ch < 64; ch++) {
        const int s = ch & 1;
        const uint32_t aS = sbase + s * (A_FLOATS * 4);
        const uint32_t bS = sbase + 2 * A_FLOATS * 4 + s * (B_FLOATS * 4);

        // ---- issue global loads for chunk ch+1 (land during compute) ----
        if (ch + 1 < 64) {
            const int k0 = (ch + 1) * 32;
#pragma unroll
            for (int it = 0; it < 2; it++) {
                int idx = tid + it * 256;
                a_pre[it] = *(const float4*)(Xn + (size_t)(idx >> 3) * LEN + k0 + (idx & 7) * 4);
            }
#pragma unroll
            for (int r = 0; r < 4; r++)
                b_pre[r] = *(const float4*)(Mn + (size_t)(k0 + 4 * kq + r) * LEN + jt + 4 * jq);
        }

        // ---- compute chunk ch from stage s ----
        const uint32_t aAddr = aS + aOff;
        const uint32_t bAddr = bS + bOff;
#pragma unroll
        for (int ksp = 0; ksp < 2; ksp++) {           // k8-pairs: covers ks=2*ksp, 2*ksp+1
            uint32_t bq[4][4];
#pragma unroll
            for (int t = 0; t < 4; t++)
                ldsm_x4(bAddr + t * 1152 + ksp * 64, bq[t]);
#pragma unroll
            for (int kh = 0; kh < 2; kh++) {
                const int ks = ksp * 2 + kh;
                uint32_t af[2][4];
                ldsm_x4(aAddr + ks * 32, af[0]);
                ldsm_x4(aAddr + 2304 + ks * 32, af[1]);   // +16 rows * 144B
#pragma unroll
                for (int f = 0; f < 2; f++)
#pragma unroll
                    for (int t = 0; t < 4; t++)
                        mma_tf32(acc[f][t], af[f], bq[t][2 * kh], bq[t][2 * kh + 1]);
            }
        }

        // ---- commit chunk ch+1 into the other stage ----
        if (ch + 1 < 64) {
            float* As = smem + (s ^ 1) * A_FLOATS;
            float* Bs = smem + 2 * A_FLOATS + (s ^ 1) * B_FLOATS;
#pragma unroll
            for (int it = 0; it < 2; it++) {
                int idx = tid + it * 256;
                float4 v = a_pre[it];
                v.x = tf32_rn(v.x); v.y = tf32_rn(v.y);
                v.z = tf32_rn(v.z); v.w = tf32_rn(v.w);
                *(float4*)&As[(idx >> 3) * AROW + (idx & 7) * 4] = v;
            }
#pragma unroll
            for (int e = 0; e < 4; e++) {
                float4 w;
                w.x = tf32_rn(((const float*)&b_pre[0])[e]);
                w.y = tf32_rn(((const float*)&b_pre[1])[e]);
                w.z = tf32_rn(((const float*)&b_pre[2])[e]);
                w.w = tf32_rn(((const float*)&b_pre[3])[e]);
                *(float4*)&Bs[(4 * jq + e) * AROW + 4 * kq] = w;
            }
            __syncthreads();
        }
    }

    // ---- epilogue: D[c][j] -> Y[c][jt+j] ----
    const int r0 = lane >> 2, cp = (lane & 3) * 2;
#pragma unroll
    for (int f = 0; f < 2; f++) {
        const int c = c0w + f * 16 + r0;
#pragma unroll
        for (int t = 0; t < 4; t++) {
            const int j = jt + n0w + t * 8 + cp;
            *(float2*)(Yn + (size_t)c * LEN + j) =
                make_float2(acc[f][t][0], acc[f][t][1]);
            *(float2*)(Yn + (size_t)(c + 8) * LEN + j) =
                make_float2(acc[f][t][2], acc[f][t][3]);
        }
    }
}

// ---------------------------------------------------------------------------
// Projection (SIMT, known-good): out[n][o][l] = sum_c W[o][c]*cat[n][c][l] + b[o]
// ---------------------------------------------------------------------------
__global__ __launch_bounds__(256, 2)
void project_kernel(const float* __restrict__ X,
                    const float* __restrict__ Y1,
                    const float* __restrict__ Y2,
                    const float* __restrict__ W,
                    const float* __restrict__ bias,
                    float* __restrict__ out)
{
    __shared__ float Ws[16][132];
    __shared__ float Cs[16][128];

    const int n  = blockIdx.y;
    const int jt = blockIdx.x * 128;

    const float* Xn  = X  + (size_t)n * CH * LEN;
    const float* Y1n = Y1 + (size_t)n * CH * LEN;
    const float* Y2n = Y2 + (size_t)n * CH * LEN;
    float*       On  = out + (size_t)n * OCH * LEN;

    const int tid  = threadIdx.x;
    const int row0 = (tid >> 4) * 8;
    const int col0 = (tid & 15) * 8;

    float acc[8][8];
#pragma unroll
    for (int i = 0; i < 8; i++)
#pragma unroll
        for (int j = 0; j < 8; j++) acc[i][j] = 0.0f;

    for (int k0 = 0; k0 < KCAT; k0 += 16) {
#pragma unroll
        for (int it = 0; it < 2; it++) {
            int idx = tid + it * 256;
            int o   = idx >> 2;
            int kq  = idx & 3;
            float4 v = *(const float4*)(W + (size_t)o * KCAT + k0 + kq * 4);
            Ws[kq * 4 + 0][o] = v.x;
            Ws[kq * 4 + 1][o] = v.y;
            Ws[kq * 4 + 2][o] = v.z;
            Ws[kq * 4 + 3][o] = v.w;
        }
#pragma unroll
        for (int it = 0; it < 2; it++) {
            int idx = tid + it * 256;
            int r   = idx >> 5;
            int q   = idx & 31;
            int c   = k0 + r;
            const float* src;
            if (c < CH)            src = Xn  + (size_t)c * LEN;
            else if (c < 2 * CH)   src = Y1n + (size_t)(c - CH) * LEN;
            else                   src = Y2n + (size_t)(c - 2 * CH) * LEN;
            *(float4*)&Cs[r][q * 4] = *(const float4*)(src + jt + q * 4);
        }
        __syncthreads();

#pragma unroll
        for (int kk = 0; kk < 16; kk++) {
            float a[8], b[8];
            *(float4*)&a[0] = *(const float4*)&Ws[kk][row0];
            *(float4*)&a[4] = *(const float4*)&Ws[kk][row0 + 4];
            *(float4*)&b[0] = *(const float4*)&Cs[kk][col0];
            *(float4*)&b[4] = *(const float4*)&Cs[kk][col0 + 4];
#pragma unroll
            for (int i = 0; i < 8; i++)
#pragma unroll
                for (int j = 0; j < 8; j++)
                    acc[i][j] = fmaf(a[i], b[j], acc[i][j]);
        }
        __syncthreads();
    }

#pragma unroll
    for (int i = 0; i < 8; i++) {
        float bv = __ldg(bias + row0 + i);
        float* dst = On + (size_t)(row0 + i) * LEN + jt + col0;
        *(float4*)(dst)     = make_float4(acc[i][0] + bv, acc[i][1] + bv,
                                          acc[i][2] + bv, acc[i][3] + bv);
        *(float4*)(dst + 4) = make_float4(acc[i][4] + bv, acc[i][5] + bv,
                                          acc[i][6] + bv, acc[i][7] + bv);
    }
}

// ---------------------------------------------------------------------------
extern "C" void kernel_launch(void* const* d_in, const int* in_sizes, int n_in,
                              void* d_out, int out_size)
{
    const float* x = (const float*)d_in[0];   // (32, 64, 2048)
    const float* m = (const float*)d_in[1];   // (32, 2048, 2048)
    const float* W = (const float*)d_in[2];   // (128, 192)
    const float* b = (const float*)d_in[3];   // (128,)
    float* out = (float*)d_out;               // (32, 128, 2048)

    float* y1;  cudaGetSymbolAddress((void**)&y1, g_y1);
    float* y2;  cudaGetSymbolAddress((void**)&y2, g_y2);

    const int smem_bytes = SMEM_FLOATS * 4;   // 55296
    cudaFuncSetAttribute(propagate_mma,
                         cudaFuncAttributeMaxDynamicSharedMemorySize, smem_bytes);

    dim3 pgrid(LEN / 128, NBATCH);   // 16 x 32 = 512 CTAs
    propagate_mma<<<pgrid, 256, smem_bytes>>>(x,  m, y1);
    propagate_mma<<<pgrid, 256, smem_bytes>>>(y1, m, y2);

    dim3 ogrid(LEN / 128, NBATCH);
    project_kernel<<<ogrid, 256>>>(x, y1, y2, W, b, out);
}